// round 6
// baseline (speedup 1.0000x reference)
#include <cuda_runtime.h>
#include <cstdint>

#define BATCH 128
#define SEQ   512
#define IDIM  256
#define HDIM  512
#define G4    2048

// ---- persistent scan tiling ----
#define NBLK  128     // 4 batch-tiles x 32 j-tiles; all co-resident
#define NTHR  1024    // 32 warps -> 8 warps/SMSP
#define BJ    16      // j per block
#define BB    32      // batches per block
#define WROW  528     // weight row: 4 quarters x (128 + 4 pad) floats
#define QOFF  132     // quarter offset inside weight row
#define GOFF  (16*WROW)  // gate offset in sWg
#define SROW  36      // staging row floats (32 + 4 pad)
#define QSTR  1156    // staging quarter stride (4-bank shift per quarter)
#define RSTR  544     // sred gate stride (bl*17 + jl, padded)
#define RSET  2720    // sred per-publisher set (5 gates)
#define SMEM_SCAN ((80*WROW + 8*QSTR) * 4)

// ---- device-global scratch (no cudaMalloc allowed) ----
__device__ float g_h[2][BATCH][HDIM];
__device__ float g_c[2][BATCH][HDIM];
__device__ float g_u[SEQ][BATCH][G4];      // precomputed input projection
__device__ unsigned g_bar[2];              // [0]=count, [1]=generation

__device__ __forceinline__ unsigned long long fma2(unsigned long long a,
                                                   unsigned long long b,
                                                   unsigned long long c) {
    unsigned long long d;
    asm("fma.rn.f32x2 %0, %1, %2, %3;" : "=l"(d) : "l"(a), "l"(b), "l"(c));
    return d;
}
__device__ __forceinline__ float red2(unsigned long long a) {
    return __uint_as_float((unsigned)a) + __uint_as_float((unsigned)(a >> 32));
}
__device__ __forceinline__ float sigm(float x) {
    return 1.0f / (1.0f + __expf(-x));
}

// =====================================================================
// Kernel 1: u_pre[s][b][g] = inputs[b][s][:] . U_all_w[g][:] + U_all_b[g]
// 64x64 tile, 128 threads, thread = 4m x 8n, k-packed f32x2.
// =====================================================================
__global__ void __launch_bounds__(128)
u_gemm_kernel(const float* __restrict__ X, const float* __restrict__ Uw,
              const float* __restrict__ Ub) {
    __shared__ float As[64][36];
    __shared__ float Bs[64][36];
    const int g0 = blockIdx.x * 64;
    const int r0 = blockIdx.y * 64;
    const int tid = threadIdx.x;
    const int tx = tid & 7;
    const int ty = tid >> 3;

    unsigned long long acc[4][8] = {};

    for (int k0 = 0; k0 < IDIM; k0 += 32) {
#pragma unroll
        for (int q = 0; q < 4; ++q) {
            int idx = tid + q * 128;
            int row = idx >> 3;
            int c4  = (idx & 7) << 2;
            *(float4*)&As[row][c4] = *(const float4*)&X[(size_t)(r0 + row) * IDIM + k0 + c4];
            *(float4*)&Bs[row][c4] = *(const float4*)&Uw[(size_t)(g0 + row) * IDIM + k0 + c4];
        }
        __syncthreads();
#pragma unroll
        for (int k = 0; k < 32; k += 2) {
            unsigned long long a[4], b[8];
#pragma unroll
            for (int mi = 0; mi < 4; ++mi) a[mi] = *(const unsigned long long*)&As[ty * 4 + mi][k];
#pragma unroll
            for (int ni = 0; ni < 8; ++ni) b[ni] = *(const unsigned long long*)&Bs[tx + ni * 8][k];
#pragma unroll
            for (int mi = 0; mi < 4; ++mi)
#pragma unroll
                for (int ni = 0; ni < 8; ++ni)
                    acc[mi][ni] = fma2(a[mi], b[ni], acc[mi][ni]);
        }
        __syncthreads();
    }
#pragma unroll
    for (int mi = 0; mi < 4; ++mi) {
        int r = r0 + ty * 4 + mi;
        int b = r >> 9;
        int s = r & 511;
        float* orow = &g_u[s][b][0];
#pragma unroll
        for (int ni = 0; ni < 8; ++ni) {
            int g = g0 + tx + ni * 8;
            orow[g] = red2(acc[mi][ni]) + Ub[g];
        }
    }
}

// =====================================================================
// Kernel 2: persistent scan. 128 CTAs x 1024 threads (8 warps/SMSP).
// Thread = 2b x 2j x (quarter ws, lane-half h): k covered = 64 per thread,
// interleaved at 4-float granularity (kk = 4h + 8i within each chunk).
// warp = jp(0..7) x ws(0..3); lane = bg(0..15) x h.
// 8 partials per output: shfl(1) folds h, ws=1..3 publish, ws=0 finishes.
// =====================================================================
__global__ void __launch_bounds__(NTHR, 1)
timelstm_scan_kernel(const float* __restrict__ Wall, const float* __restrict__ Wallb,
                     const float* __restrict__ Wd,   const float* __restrict__ Wdb,
                     const float* __restrict__ ts,   float* __restrict__ out) {
    extern __shared__ float sm[];
    float* sWg  = sm;                        // 64 rows (4 gates x 16 j) x WROW
    float* sWd  = sWg + 64 * WROW;           // 16 rows x WROW  (= sWg + 64*WROW)
    float* stgh = sWd + 16 * WROW;           // 4 quarters x 32 x SROW
    float* stgc = stgh + 4 * QSTR;
    float* sred = stgh;                      // 3 sets x RSET floats, reuses staging

    const int tid  = threadIdx.x;
    const int lane = tid & 31;
    const int warp = tid >> 5;
    const int bg   = lane >> 1;              // 0..15
    const int h    = lane & 1;               // k-interleave bit
    const int jp   = warp & 7;               // 0..7
    const int ws   = warp >> 3;              // quarter 0..3

    const int jt = blockIdx.x >> 2;
    const int bt = blockIdx.x & 3;
    const int j0 = jt * BJ;
    const int b0 = bt * BB;

    const int bl0 = bg * 2;                  // local batches bl0, bl0+1
    const int h4  = h * 4;

    // ---- preload weights into SMEM with quarter-padded rows ----
    for (int idx = tid; idx < 64 * 128; idx += NTHR) {
        int row = idx >> 7;
        int kf  = (idx & 127) << 2;
        int qtr = kf >> 7, kin = kf & 127;
        int g = row >> 4, jl = row & 15;
        *(float4*)&sWg[row * WROW + qtr * QOFF + kin] =
            *(const float4*)&Wall[(size_t)(g * HDIM + j0 + jl) * HDIM + kf];
    }
    for (int idx = tid; idx < 16 * 128; idx += NTHR) {
        int row = idx >> 7;
        int kf  = (idx & 127) << 2;
        int qtr = kf >> 7, kin = kf & 127;
        *(float4*)&sWd[row * WROW + qtr * QOFF + kin] =
            *(const float4*)&Wd[(size_t)(j0 + row) * HDIM + kf];
    }
    // epilogue j for finisher lanes (ws==0): jle = jp + h*8
    const int jle = jp + h * 8;
    const int je  = j0 + jle;
    const float bF  = Wallb[0 * HDIM + je];
    const float bI  = Wallb[1 * HDIM + je];
    const float bO  = Wallb[2 * HDIM + je];
    const float bCt = Wallb[3 * HDIM + je];
    const float bD  = Wdb[je];
    __syncthreads();

    // single weight base; everything else via constant offsets:
    //   gate g: +g*GOFF ; j=jp+8: +8*WROW ; decay: +64*WROW (sWd)
    const float* wA = sWg + jp * WROW + ws * QOFF + h4;
    // staging bases (c array at +4*QSTR constant offset)
    const float* hb = stgh + ws * QSTR + bl0 * SROW + h4;

    // staging writer mapping: 1 float4 per thread per array per chunk
    const int sqtr = tid >> 8;
    const int srw  = (tid >> 3) & 31;
    const int sc4  = (tid & 7) << 2;
    float* sdsth = stgh + sqtr * QSTR + srw * SROW + sc4;
    const float* hsrc0 = &g_h[0][b0 + srw][sqtr * 128 + sc4];
    const float* csrc0 = &g_c[0][b0 + srw][sqtr * 128 + sc4];
    const float* hsrc1 = &g_h[1][b0 + srw][sqtr * 128 + sc4];
    const float* csrc1 = &g_c[1][b0 + srw][sqtr * 128 + sc4];

    for (int s = 0; s < SEQ; ++s) {
        const int cur = s & 1, nxt = cur ^ 1;
        const float* hsrc = cur ? hsrc1 : hsrc0;
        const float* csrc = cur ? csrc1 : csrc0;

        unsigned long long aF[2][2] = {}, aI[2][2] = {}, aO[2][2] = {},
                           aC[2][2] = {}, aD[2][2] = {};

#pragma unroll 1
        for (int kci = 0; kci < 4; ++kci) {
            __syncthreads();   // previous chunk consumed / sred free
            *(float4*)sdsth            = __ldcg((const float4*)(hsrc + kci * 32));
            *(float4*)(sdsth + 4*QSTR) = __ldcg((const float4*)(csrc + kci * 32));
            __syncthreads();

            const float* wp = wA + kci * 32;
            const float* hp = hb + kci * 0;   // staging holds only current chunk
#pragma unroll
            for (int i = 0; i < 4; ++i) {
                const int off = 8 * i;
                ulonglong2 hv0 = *(const ulonglong2*)(hp + off);
                ulonglong2 hv1 = *(const ulonglong2*)(hp + SROW + off);
                ulonglong2 cv0 = *(const ulonglong2*)(hp + 4 * QSTR + off);
                ulonglong2 cv1 = *(const ulonglong2*)(hp + 4 * QSTR + SROW + off);
                // ---- j = jp (js=0) ----
                {
                    ulonglong2 vF = *(const ulonglong2*)(wp + 0 * GOFF + off);
                    ulonglong2 vI = *(const ulonglong2*)(wp + 1 * GOFF + off);
                    ulonglong2 vO = *(const ulonglong2*)(wp + 2 * GOFF + off);
                    ulonglong2 vC = *(const ulonglong2*)(wp + 3 * GOFF + off);
                    ulonglong2 vD = *(const ulonglong2*)(wp + 64 * WROW + off);
                    aF[0][0] = fma2(hv0.x, vF.x, aF[0][0]); aF[0][0] = fma2(hv0.y, vF.y, aF[0][0]);
                    aF[0][1] = fma2(hv1.x, vF.x, aF[0][1]); aF[0][1] = fma2(hv1.y, vF.y, aF[0][1]);
                    aI[0][0] = fma2(hv0.x, vI.x, aI[0][0]); aI[0][0] = fma2(hv0.y, vI.y, aI[0][0]);
                    aI[0][1] = fma2(hv1.x, vI.x, aI[0][1]); aI[0][1] = fma2(hv1.y, vI.y, aI[0][1]);
                    aO[0][0] = fma2(hv0.x, vO.x, aO[0][0]); aO[0][0] = fma2(hv0.y, vO.y, aO[0][0]);
                    aO[0][1] = fma2(hv1.x, vO.x, aO[0][1]); aO[0][1] = fma2(hv1.y, vO.y, aO[0][1]);
                    aC[0][0] = fma2(hv0.x, vC.x, aC[0][0]); aC[0][0] = fma2(hv0.y, vC.y, aC[0][0]);
                    aC[0][1] = fma2(hv1.x, vC.x, aC[0][1]); aC[0][1] = fma2(hv1.y, vC.y, aC[0][1]);
                    aD[0][0] = fma2(cv0.x, vD.x, aD[0][0]); aD[0][0] = fma2(cv0.y, vD.y, aD[0][0]);
                    aD[0][1] = fma2(cv1.x, vD.x, aD[0][1]); aD[0][1] = fma2(cv1.y, vD.y, aD[0][1]);
                }
                // ---- j = jp+8 (js=1) ----
                {
                    ulonglong2 vF = *(const ulonglong2*)(wp + 8 * WROW + 0 * GOFF + off);
                    ulonglong2 vI = *(const ulonglong2*)(wp + 8 * WROW + 1 * GOFF + off);
                    ulonglong2 vO = *(const ulonglong2*)(wp + 8 * WROW + 2 * GOFF + off);
                    ulonglong2 vC = *(const ulonglong2*)(wp + 8 * WROW + 3 * GOFF + off);
                    ulonglong2 vD = *(const ulonglong2*)(wp + 72 * WROW + off);
                    aF[1][0] = fma2(hv0.x, vF.x, aF[1][0]); aF[1][0] = fma2(hv0.y, vF.y, aF[1][0]);
                    aF[1][1] = fma2(hv1.x, vF.x, aF[1][1]); aF[1][1] = fma2(hv1.y, vF.y, aF[1][1]);
                    aI[1][0] = fma2(hv0.x, vI.x, aI[1][0]); aI[1][0] = fma2(hv0.y, vI.y, aI[1][0]);
                    aI[1][1] = fma2(hv1.x, vI.x, aI[1][1]); aI[1][1] = fma2(hv1.y, vI.y, aI[1][1]);
                    aO[1][0] = fma2(hv0.x, vO.x, aO[1][0]); aO[1][0] = fma2(hv0.y, vO.y, aO[1][0]);
                    aO[1][1] = fma2(hv1.x, vO.x, aO[1][1]); aO[1][1] = fma2(hv1.y, vO.y, aO[1][1]);
                    aC[1][0] = fma2(hv0.x, vC.x, aC[1][0]); aC[1][0] = fma2(hv0.y, vC.y, aC[1][0]);
                    aC[1][1] = fma2(hv1.x, vC.x, aC[1][1]); aC[1][1] = fma2(hv1.y, vC.y, aC[1][1]);
                    aD[1][0] = fma2(cv0.x, vD.x, aD[1][0]); aD[1][0] = fma2(cv0.y, vD.y, aD[1][0]);
                    aD[1][1] = fma2(cv1.x, vD.x, aD[1][1]); aD[1][1] = fma2(cv1.y, vD.y, aD[1][1]);
                }
            }
        }

        // ---- fold lane pairs (h) -> quarter sums ----
        float p[2][2][5];
#pragma unroll
        for (int js = 0; js < 2; ++js)
#pragma unroll
            for (int bs = 0; bs < 2; ++bs) {
                p[js][bs][0] = red2(aF[js][bs]);
                p[js][bs][1] = red2(aI[js][bs]);
                p[js][bs][2] = red2(aO[js][bs]);
                p[js][bs][3] = red2(aC[js][bs]);
                p[js][bs][4] = red2(aD[js][bs]);
            }
#pragma unroll
        for (int js = 0; js < 2; ++js)
#pragma unroll
            for (int bs = 0; bs < 2; ++bs)
#pragma unroll
                for (int g = 0; g < 5; ++g)
                    p[js][bs][g] += __shfl_xor_sync(0xffffffffu, p[js][bs][g], 1);

        __syncthreads();            // all staging reads done; sred free

        // epilogue operand loads (finisher lanes), overlapped with publish sync
        float uf[2], ui[2], uo[2], uct[2], tv[2], cold[2];
        if (ws == 0) {
#pragma unroll
            for (int bs = 0; bs < 2; ++bs) {
                int be = b0 + bl0 + bs;
                const float* ub = &g_u[s][be][0];
                uf[bs]  = ub[je];
                ui[bs]  = ub[HDIM + je];
                uo[bs]  = ub[2 * HDIM + je];
                uct[bs] = ub[3 * HDIM + je];
                tv[bs]  = ts[(size_t)be * SEQ + s];
                cold[bs] = __ldcg(&g_c[cur][be][je]);
            }
        } else {
            // publish own-j half (js == h) for both batches
            float* rp = sred + (ws - 1) * RSET;
#pragma unroll
            for (int bs = 0; bs < 2; ++bs) {
                int bl = bl0 + bs;
#pragma unroll
                for (int g = 0; g < 5; ++g)
                    rp[g * RSTR + bl * 17 + jle] = p[h][bs][g];
            }
        }
        __syncthreads();
        if (ws == 0) {
#pragma unroll
            for (int bs = 0; bs < 2; ++bs) {
                int bl = bl0 + bs;
                int be = b0 + bl;
                int ri = bl * 17 + jle;
                float F  = p[h][bs][0] + sred[0*RSET + 0*RSTR + ri] + sred[1*RSET + 0*RSTR + ri] + sred[2*RSET + 0*RSTR + ri] + bF  + uf[bs];
                float I_ = p[h][bs][1] + sred[0*RSET + 1*RSTR + ri] + sred[1*RSET + 1*RSTR + ri] + sred[2*RSET + 1*RSTR + ri] + bI  + ui[bs];
                float O_ = p[h][bs][2] + sred[0*RSET + 2*RSTR + ri] + sred[1*RSET + 2*RSTR + ri] + sred[2*RSET + 2*RSTR + ri] + bO  + uo[bs];
                float Ct = p[h][bs][3] + sred[0*RSET + 3*RSTR + ri] + sred[1*RSET + 3*RSTR + ri] + sred[2*RSET + 3*RSTR + ri] + bCt + uct[bs];
                float D  = p[h][bs][4] + sred[0*RSET + 4*RSTR + ri] + sred[1*RSET + 4*RSTR + ri] + sred[2*RSET + 4*RSTR + ri] + bD;
                float f   = sigm(F);
                float ii  = sigm(I_);
                float oo  = sigm(O_);
                float ct  = sigm(Ct);
                float cs1 = tanhf(D);
                float cadj = cold[bs] + cs1 * (tv[bs] - 1.0f);   // c - cs1 + cs1*t
                float cnew = f * cadj + ii * ct;
                float hnew = oo * tanhf(cnew);
                g_c[nxt][be][je] = cnew;
                g_h[nxt][be][je] = hnew;
                out[((size_t)be * SEQ + s) * HDIM + je] = hnew;
            }
        }

        // ---- grid barrier ----
        __syncthreads();
        if (tid == 0) {
            volatile unsigned* vgen = &g_bar[1];
            unsigned gen = *vgen;
            __threadfence();
            if (atomicAdd(&g_bar[0], 1u) == NBLK - 1u) {
                g_bar[0] = 0u;
                __threadfence();
                *vgen = gen + 1u;
            } else {
                while (*vgen == gen) { }
            }
            __threadfence();
        }
        __syncthreads();
    }
}

// =====================================================================
extern "C" void kernel_launch(void* const* d_in, const int* in_sizes, int n_in,
                              void* d_out, int out_size) {
    const float* X     = (const float*)d_in[0];   // inputs   [B,S,I]
    const float* T     = (const float*)d_in[1];   // timestamps [B,S]
    const float* Wall  = (const float*)d_in[2];   // W_all_w  [4H,H]
    const float* Wallb = (const float*)d_in[3];   // W_all_b  [4H]
    const float* Uw    = (const float*)d_in[4];   // U_all_w  [4H,I]
    const float* Ubb   = (const float*)d_in[5];   // U_all_b  [4H]
    const float* Wd    = (const float*)d_in[6];   // W_d_w    [H,H]
    const float* Wdb   = (const float*)d_in[7];   // W_d_b    [H]
    float* out = (float*)d_out;

    void *hp, *cp, *bp;
    cudaGetSymbolAddress(&hp, g_h);
    cudaGetSymbolAddress(&cp, g_c);
    cudaGetSymbolAddress(&bp, g_bar);
    cudaMemsetAsync(hp, 0, sizeof(float) * 2 * BATCH * HDIM, 0);
    cudaMemsetAsync(cp, 0, sizeof(float) * 2 * BATCH * HDIM, 0);
    cudaMemsetAsync(bp, 0, sizeof(unsigned) * 2, 0);

    dim3 ugrid(G4 / 64, (BATCH * SEQ) / 64);
    u_gemm_kernel<<<ugrid, 128>>>(X, Uw, Ubb);

    cudaFuncSetAttribute(timelstm_scan_kernel,
                         cudaFuncAttributeMaxDynamicSharedMemorySize, SMEM_SCAN);
    timelstm_scan_kernel<<<NBLK, NTHR, SMEM_SCAN>>>(Wall, Wallb, Wd, Wdb, T, out);
}

// round 7
// speedup vs baseline: 1.0545x; 1.0545x over previous
#include <cuda_runtime.h>
#include <cstdint>

#define BATCH 128
#define SEQ   512
#define IDIM  256
#define HDIM  512
#define G4    2048

// ---- persistent scan tiling ----
#define NBLK  128     // 4 batch-tiles x 32 j-tiles; all co-resident
#define NTHR  512     // 16 warps, 4 per SMSP, 128 regs/thread budget
#define BJ    16      // j per block
#define BB    32      // batches per block
#define WROW  528     // weight row: 4 quarters x (128 + 4 pad) floats
#define QOFF  132     // quarter offset inside weight row (4-bank shift)
#define GOFF  (16*WROW)  // gate offset in sWg (rows 0..63 gates, 64..79 decay)
#define SROW  36      // staging row floats (16 data + pad; 4-bank/row shift)
#define QSTR  1160    // staging quarter stride (== 8 mod 32 -> 8-bank/quarter shift)
#define SMEM_SCAN ((80*WROW + 8*QSTR) * 4)   // 206 KB

// ---- device-global scratch (no cudaMalloc allowed) ----
__device__ float g_h[2][BATCH][HDIM];
__device__ float g_c[2][BATCH][HDIM];
__device__ float g_u[SEQ][BATCH][G4];      // precomputed input projection
__device__ unsigned g_bar[2];              // [0]=count, [1]=generation

__device__ __forceinline__ unsigned long long fma2(unsigned long long a,
                                                   unsigned long long b,
                                                   unsigned long long c) {
    unsigned long long d;
    asm("fma.rn.f32x2 %0, %1, %2, %3;" : "=l"(d) : "l"(a), "l"(b), "l"(c));
    return d;
}
__device__ __forceinline__ float red2(unsigned long long a) {
    return __uint_as_float((unsigned)a) + __uint_as_float((unsigned)(a >> 32));
}
__device__ __forceinline__ float sigm(float x) {
    return 1.0f / (1.0f + __expf(-x));
}

// =====================================================================
// Kernel 1: u_pre[s][b][g] = inputs[b][s][:] . U_all_w[g][:] + U_all_b[g]
// 64x64 tile, 128 threads, thread = 4m x 8n, k-packed f32x2. (unchanged)
// =====================================================================
__global__ void __launch_bounds__(128)
u_gemm_kernel(const float* __restrict__ X, const float* __restrict__ Uw,
              const float* __restrict__ Ub) {
    __shared__ float As[64][36];
    __shared__ float Bs[64][36];
    const int g0 = blockIdx.x * 64;
    const int r0 = blockIdx.y * 64;
    const int tid = threadIdx.x;
    const int tx = tid & 7;
    const int ty = tid >> 3;

    unsigned long long acc[4][8] = {};

    for (int k0 = 0; k0 < IDIM; k0 += 32) {
#pragma unroll
        for (int q = 0; q < 4; ++q) {
            int idx = tid + q * 128;
            int row = idx >> 3;
            int c4  = (idx & 7) << 2;
            *(float4*)&As[row][c4] = *(const float4*)&X[(size_t)(r0 + row) * IDIM + k0 + c4];
            *(float4*)&Bs[row][c4] = *(const float4*)&Uw[(size_t)(g0 + row) * IDIM + k0 + c4];
        }
        __syncthreads();
#pragma unroll
        for (int k = 0; k < 32; k += 2) {
            unsigned long long a[4], b[8];
#pragma unroll
            for (int mi = 0; mi < 4; ++mi) a[mi] = *(const unsigned long long*)&As[ty * 4 + mi][k];
#pragma unroll
            for (int ni = 0; ni < 8; ++ni) b[ni] = *(const unsigned long long*)&Bs[tx + ni * 8][k];
#pragma unroll
            for (int mi = 0; mi < 4; ++mi)
#pragma unroll
                for (int ni = 0; ni < 8; ++ni)
                    acc[mi][ni] = fma2(a[mi], b[ni], acc[mi][ni]);
        }
        __syncthreads();
    }
#pragma unroll
    for (int mi = 0; mi < 4; ++mi) {
        int r = r0 + ty * 4 + mi;
        int b = r >> 9;
        int s = r & 511;
        float* orow = &g_u[s][b][0];
#pragma unroll
        for (int ni = 0; ni < 8; ++ni) {
            int g = g0 + tx + ni * 8;
            orow[g] = red2(acc[mi][ni]) + Ub[g];
        }
    }
}

// =====================================================================
// Kernel 2: persistent scan. 128 CTAs x 512 threads (16 warps).
// Thread = 4 batches x 1 j x 1 k-quarter. warp = j-local (0..15);
// lane = kq*8 + bg. 20 packed accumulators.
// k-quarter reduction via shfl.xor(8) + shfl.xor(16) — no SMEM exchange.
// Staging: 8 rounds/step of 16-k-per-quarter, register-prefetched one
// round ahead to hide LDG latency. Weights SMEM-resident all 512 steps.
// =====================================================================
__global__ void __launch_bounds__(NTHR, 1)
timelstm_scan_kernel(const float* __restrict__ Wall, const float* __restrict__ Wallb,
                     const float* __restrict__ Wd,   const float* __restrict__ Wdb,
                     const float* __restrict__ ts,   float* __restrict__ out) {
    extern __shared__ float sm[];
    float* sWg = sm;                         // 80 rows x WROW (64 gate + 16 decay)
    float* stg = sm + 80 * WROW;             // h: 4*QSTR, c: +4*QSTR

    const int tid  = threadIdx.x;
    const int lane = tid & 31;
    const int warp = tid >> 5;               // = j-local 0..15
    const int kq   = lane >> 3;              // k-quarter 0..3
    const int bg   = lane & 7;               // batch group 0..7

    const int jt = blockIdx.x >> 2;
    const int bt = blockIdx.x & 3;
    const int j0 = jt * BJ;
    const int b0 = bt * BB;
    const int j  = j0 + warp;

    // ---- preload weights into SMEM with quarter-padded rows ----
    for (int idx = tid; idx < 80 * 128; idx += NTHR) {
        int row = idx >> 7;
        int kf  = (idx & 127) << 2;
        int qtr = kf >> 7, kin = kf & 127;
        const float* srcp = (row < 64)
            ? &Wall[(size_t)((row >> 4) * HDIM + j0 + (row & 15)) * HDIM + kf]
            : &Wd[(size_t)(j0 + row - 64) * HDIM + kf];
        *(float4*)&sWg[row * WROW + qtr * QOFF + kin] = *(const float4*)srcp;
    }
    const float bF  = Wallb[0 * HDIM + j];
    const float bI  = Wallb[1 * HDIM + j];
    const float bO  = Wallb[2 * HDIM + j];
    const float bCt = Wallb[3 * HDIM + j];
    const float bD  = Wdb[j];
    __syncthreads();

    // weight base: row=warp, quarter=kq; gate g at +g*GOFF, decay at +64*WROW
    const float* wB = sWg + warp * WROW + kq * QOFF;
    // state bases: rows bg+8q at +q*288; c array at +4*QSTR
    const float* hb = stg + kq * QSTR + bg * SROW;

    // staging writer mapping: 1 float4 per thread per array per round
    const int sqtr = tid >> 7;                    // quarter (const per warp)
    const int srow = ((tid >> 5) & 3) * 8 + bg;   // 0..31 (uses lane&7 = bg)
    const int sc4  = (lane >> 3) << 2;            // 0,4,8,12
    float* sdst = stg + sqtr * QSTR + srow * SROW + sc4;
    const float* hS0 = &g_h[0][b0 + srow][sqtr * 128 + sc4];
    const float* cS0 = &g_c[0][b0 + srow][sqtr * 128 + sc4];
    const float* hS1 = &g_h[1][b0 + srow][sqtr * 128 + sc4];
    const float* cS1 = &g_c[1][b0 + srow][sqtr * 128 + sc4];

    for (int s = 0; s < SEQ; ++s) {
        const int cur = s & 1, nxt = cur ^ 1;
        const float* hsrc = cur ? hS1 : hS0;
        const float* csrc = cur ? cS1 : cS0;

        unsigned long long aF0 = 0, aF1 = 0, aF2 = 0, aF3 = 0;
        unsigned long long aI0 = 0, aI1 = 0, aI2 = 0, aI3 = 0;
        unsigned long long aO0 = 0, aO1 = 0, aO2 = 0, aO3 = 0;
        unsigned long long aC0 = 0, aC1 = 0, aC2 = 0, aC3 = 0;
        unsigned long long aD0 = 0, aD1 = 0, aD2 = 0, aD3 = 0;

        float4 hr = __ldcg((const float4*)hsrc);
        float4 cr = __ldcg((const float4*)csrc);

#pragma unroll 1
        for (int r = 0; r < 8; ++r) {
            __syncthreads();                 // previous round fully consumed
            *(float4*)sdst              = hr;
            *(float4*)(sdst + 4 * QSTR) = cr;
            if (r < 7) {
                hr = __ldcg((const float4*)(hsrc + (r + 1) * 16));
                cr = __ldcg((const float4*)(csrc + (r + 1) * 16));
            }
            __syncthreads();                 // staged data visible

            const float* wr = wB + r * 16;
#pragma unroll
            for (int kk = 0; kk < 16; kk += 4) {
                ulonglong2 hv0 = *(const ulonglong2*)(hb + kk);
                ulonglong2 hv1 = *(const ulonglong2*)(hb + 288 + kk);
                ulonglong2 hv2 = *(const ulonglong2*)(hb + 576 + kk);
                ulonglong2 hv3 = *(const ulonglong2*)(hb + 864 + kk);
                ulonglong2 cv0 = *(const ulonglong2*)(hb + 4 * QSTR + kk);
                ulonglong2 cv1 = *(const ulonglong2*)(hb + 4 * QSTR + 288 + kk);
                ulonglong2 cv2 = *(const ulonglong2*)(hb + 4 * QSTR + 576 + kk);
                ulonglong2 cv3 = *(const ulonglong2*)(hb + 4 * QSTR + 864 + kk);
                ulonglong2 vF = *(const ulonglong2*)(wr + 0 * GOFF + kk);
                aF0 = fma2(hv0.x, vF.x, aF0); aF0 = fma2(hv0.y, vF.y, aF0);
                aF1 = fma2(hv1.x, vF.x, aF1); aF1 = fma2(hv1.y, vF.y, aF1);
                aF2 = fma2(hv2.x, vF.x, aF2); aF2 = fma2(hv2.y, vF.y, aF2);
                aF3 = fma2(hv3.x, vF.x, aF3); aF3 = fma2(hv3.y, vF.y, aF3);
                ulonglong2 vI = *(const ulonglong2*)(wr + 1 * GOFF + kk);
                aI0 = fma2(hv0.x, vI.x, aI0); aI0 = fma2(hv0.y, vI.y, aI0);
                aI1 = fma2(hv1.x, vI.x, aI1); aI1 = fma2(hv1.y, vI.y, aI1);
                aI2 = fma2(hv2.x, vI.x, aI2); aI2 = fma2(hv2.y, vI.y, aI2);
                aI3 = fma2(hv3.x, vI.x, aI3); aI3 = fma2(hv3.y, vI.y, aI3);
                ulonglong2 vO = *(const ulonglong2*)(wr + 2 * GOFF + kk);
                aO0 = fma2(hv0.x, vO.x, aO0); aO0 = fma2(hv0.y, vO.y, aO0);
                aO1 = fma2(hv1.x, vO.x, aO1); aO1 = fma2(hv1.y, vO.y, aO1);
                aO2 = fma2(hv2.x, vO.x, aO2); aO2 = fma2(hv2.y, vO.y, aO2);
                aO3 = fma2(hv3.x, vO.x, aO3); aO3 = fma2(hv3.y, vO.y, aO3);
                ulonglong2 vC = *(const ulonglong2*)(wr + 3 * GOFF + kk);
                aC0 = fma2(hv0.x, vC.x, aC0); aC0 = fma2(hv0.y, vC.y, aC0);
                aC1 = fma2(hv1.x, vC.x, aC1); aC1 = fma2(hv1.y, vC.y, aC1);
                aC2 = fma2(hv2.x, vC.x, aC2); aC2 = fma2(hv2.y, vC.y, aC2);
                aC3 = fma2(hv3.x, vC.x, aC3); aC3 = fma2(hv3.y, vC.y, aC3);
                ulonglong2 vD = *(const ulonglong2*)(wr + 64 * WROW + kk);
                aD0 = fma2(cv0.x, vD.x, aD0); aD0 = fma2(cv0.y, vD.y, aD0);
                aD1 = fma2(cv1.x, vD.x, aD1); aD1 = fma2(cv1.y, vD.y, aD1);
                aD2 = fma2(cv2.x, vD.x, aD2); aD2 = fma2(cv2.y, vD.y, aD2);
                aD3 = fma2(cv3.x, vD.x, aD3); aD3 = fma2(cv3.y, vD.y, aD3);
            }
        }

        // ---- collapse packed halves ----
        float p[4][5];
        p[0][0] = red2(aF0); p[1][0] = red2(aF1); p[2][0] = red2(aF2); p[3][0] = red2(aF3);
        p[0][1] = red2(aI0); p[1][1] = red2(aI1); p[2][1] = red2(aI2); p[3][1] = red2(aI3);
        p[0][2] = red2(aO0); p[1][2] = red2(aO1); p[2][2] = red2(aO2); p[3][2] = red2(aO3);
        p[0][3] = red2(aC0); p[1][3] = red2(aC1); p[2][3] = red2(aC2); p[3][3] = red2(aC3);
        p[0][4] = red2(aD0); p[1][4] = red2(aD1); p[2][4] = red2(aD2); p[3][4] = red2(aD3);

        // epilogue operand loads issued before the shfl chain (latency overlap)
        float uf[4], ui[4], uo[4], uct[4], tv[4], cold[4];
        if (kq == 0) {
#pragma unroll
            for (int q = 0; q < 4; ++q) {
                int b = b0 + bg + 8 * q;
                const float* ub = &g_u[s][b][0];
                uf[q]  = ub[j];
                ui[q]  = ub[HDIM + j];
                uo[q]  = ub[2 * HDIM + j];
                uct[q] = ub[3 * HDIM + j];
                tv[q]  = ts[(size_t)b * SEQ + s];
                cold[q] = __ldcg(&g_c[cur][b][j]);
            }
        }

        // ---- reduce across k-quarters (lane bits 3,4) ----
#pragma unroll
        for (int q = 0; q < 4; ++q)
#pragma unroll
            for (int g = 0; g < 5; ++g) {
                p[q][g] += __shfl_xor_sync(0xffffffffu, p[q][g], 8);
                p[q][g] += __shfl_xor_sync(0xffffffffu, p[q][g], 16);
            }

        // ---- epilogue on kq==0 lanes: 4 batches x 1 j each ----
        if (kq == 0) {
#pragma unroll
            for (int q = 0; q < 4; ++q) {
                int b = b0 + bg + 8 * q;
                float F  = p[q][0] + bF  + uf[q];
                float I_ = p[q][1] + bI  + ui[q];
                float O_ = p[q][2] + bO  + uo[q];
                float Ct = p[q][3] + bCt + uct[q];
                float D  = p[q][4] + bD;
                float f   = sigm(F);
                float ii  = sigm(I_);
                float oo  = sigm(O_);
                float ct  = sigm(Ct);
                float cs1 = tanhf(D);
                float cadj = cold[q] + cs1 * (tv[q] - 1.0f);   // c - cs1 + cs1*t
                float cnew = f * cadj + ii * ct;
                float hnew = oo * tanhf(cnew);
                g_c[nxt][b][j] = cnew;
                g_h[nxt][b][j] = hnew;
                out[((size_t)b * SEQ + s) * HDIM + j] = hnew;
            }
        }

        // ---- grid barrier ----
        __syncthreads();
        if (tid == 0) {
            volatile unsigned* vgen = &g_bar[1];
            unsigned gen = *vgen;
            __threadfence();
            if (atomicAdd(&g_bar[0], 1u) == NBLK - 1u) {
                g_bar[0] = 0u;
                __threadfence();
                *vgen = gen + 1u;
            } else {
                while (*vgen == gen) { }
            }
            __threadfence();
        }
        __syncthreads();
    }
}

// =====================================================================
extern "C" void kernel_launch(void* const* d_in, const int* in_sizes, int n_in,
                              void* d_out, int out_size) {
    const float* X     = (const float*)d_in[0];   // inputs   [B,S,I]
    const float* T     = (const float*)d_in[1];   // timestamps [B,S]
    const float* Wall  = (const float*)d_in[2];   // W_all_w  [4H,H]
    const float* Wallb = (const float*)d_in[3];   // W_all_b  [4H]
    const float* Uw    = (const float*)d_in[4];   // U_all_w  [4H,I]
    const float* Ubb   = (const float*)d_in[5];   // U_all_b  [4H]
    const float* Wd    = (const float*)d_in[6];   // W_d_w    [H,H]
    const float* Wdb   = (const float*)d_in[7];   // W_d_b    [H]
    float* out = (float*)d_out;

    void *hp, *cp, *bp;
    cudaGetSymbolAddress(&hp, g_h);
    cudaGetSymbolAddress(&cp, g_c);
    cudaGetSymbolAddress(&bp, g_bar);
    cudaMemsetAsync(hp, 0, sizeof(float) * 2 * BATCH * HDIM, 0);
    cudaMemsetAsync(cp, 0, sizeof(float) * 2 * BATCH * HDIM, 0);
    cudaMemsetAsync(bp, 0, sizeof(unsigned) * 2, 0);

    dim3 ugrid(G4 / 64, (BATCH * SEQ) / 64);
    u_gemm_kernel<<<ugrid, 128>>>(X, Uw, Ubb);

    cudaFuncSetAttribute(timelstm_scan_kernel,
                         cudaFuncAttributeMaxDynamicSharedMemorySize, SMEM_SCAN);
    timelstm_scan_kernel<<<NBLK, NTHR, SMEM_SCAN>>>(Wall, Wallb, Wd, Wdb, T, out);
}

// round 9
// speedup vs baseline: 1.2501x; 1.1855x over previous
#include <cuda_runtime.h>
#include <cstdint>

#define BATCH 128
#define SEQ   512
#define IDIM  256
#define HDIM  512
#define G4    2048

// ---- persistent scan tiling ----
#define NBLK  128     // 4 batch-tiles x 32 j-tiles
#define NTHR  512     // 16 warps: warp = ks(4) x jg(4); lane = batch
#define BJ    16
#define BB    32
#define SROW  132     // staging row floats (128 + 4) -> 528B, 16B-aligned rows
#define COFF  4224    // c offset inside a staging buffer (32*132)
#define BUFS  8448    // staging buffer stride (h+c)
#define WTOT  40960   // weight floats: 80 rows x 512
#define PSTR_J 15     // part: 5 gates x 3 publishers
#define PSTR_B 241    // part: 16 j x 15 + 1 pad (odd bank stride, conflict-free)
#define SMEM_SCAN ((WTOT + 2*BUFS) * 4)   // 231424 B (<= 227KB limit)

// ---- device-global scratch (no cudaMalloc allowed) ----
__device__ float g_h[2][BATCH][HDIM];
__device__ float g_c[2][BATCH][HDIM];
__device__ float g_u[SEQ][BATCH][G4];
__device__ unsigned g_bar[2];

__device__ __forceinline__ unsigned long long fma2(unsigned long long a,
                                                   unsigned long long b,
                                                   unsigned long long c) {
    unsigned long long d;
    asm("fma.rn.f32x2 %0, %1, %2, %3;" : "=l"(d) : "l"(a), "l"(b), "l"(c));
    return d;
}
__device__ __forceinline__ float red2(unsigned long long a) {
    return __uint_as_float((unsigned)a) + __uint_as_float((unsigned)(a >> 32));
}
__device__ __forceinline__ float sigm(float x) {
    return 1.0f / (1.0f + __expf(-x));
}
__device__ __forceinline__ float tanhfast(float x) {
    float y;
    asm("tanh.approx.f32 %0, %1;" : "=f"(y) : "f"(x));
    return y;
}

// =====================================================================
// Kernel 1: u_pre[s][b][g] (unchanged from R5 best)
// =====================================================================
__global__ void __launch_bounds__(128)
u_gemm_kernel(const float* __restrict__ X, const float* __restrict__ Uw,
              const float* __restrict__ Ub) {
    __shared__ float As[64][36];
    __shared__ float Bs[64][36];
    const int g0 = blockIdx.x * 64;
    const int r0 = blockIdx.y * 64;
    const int tid = threadIdx.x;
    const int tx = tid & 7;
    const int ty = tid >> 3;

    unsigned long long acc[4][8] = {};

    for (int k0 = 0; k0 < IDIM; k0 += 32) {
#pragma unroll
        for (int q = 0; q < 4; ++q) {
            int idx = tid + q * 128;
            int row = idx >> 3;
            int c4  = (idx & 7) << 2;
            *(float4*)&As[row][c4] = *(const float4*)&X[(size_t)(r0 + row) * IDIM + k0 + c4];
            *(float4*)&Bs[row][c4] = *(const float4*)&Uw[(size_t)(g0 + row) * IDIM + k0 + c4];
        }
        __syncthreads();
#pragma unroll
        for (int k = 0; k < 32; k += 2) {
            unsigned long long a[4], b[8];
#pragma unroll
            for (int mi = 0; mi < 4; ++mi) a[mi] = *(const unsigned long long*)&As[ty * 4 + mi][k];
#pragma unroll
            for (int ni = 0; ni < 8; ++ni) b[ni] = *(const unsigned long long*)&Bs[tx + ni * 8][k];
#pragma unroll
            for (int mi = 0; mi < 4; ++mi)
#pragma unroll
                for (int ni = 0; ni < 8; ++ni)
                    acc[mi][ni] = fma2(a[mi], b[ni], acc[mi][ni]);
        }
        __syncthreads();
    }
#pragma unroll
    for (int mi = 0; mi < 4; ++mi) {
        int r = r0 + ty * 4 + mi;
        int b = r >> 9;
        int s = r & 511;
        float* orow = &g_u[s][b][0];
#pragma unroll
        for (int ni = 0; ni < 8; ++ni) {
            int g = g0 + tx + ni * 8;
            orow[g] = red2(acc[mi][ni]) + Ub[g];
        }
    }
}

// =====================================================================
// Kernel 2: persistent scan. 128 CTAs x 512 threads.
// lane = batch (32 per warp); warp = ks(4 k-slices) x jg(4 j-groups).
// Thread = 1b x 4j x 128k -> 20 packed accums. Weight LDS warp-uniform
// (pure broadcast, unpadded 160KB); state LDS 1 row/lane (4-bank row
// stride -> phase-conflict-free). Double-buffered k-quarter staging
// (1 sync/quarter, LDG prefetch overlapped). k-partials combined via
// conflict-free SMEM exchange; ks=0 warps run the epilogue with float4
// u/c loads and tanh.approx.
// =====================================================================
__global__ void __launch_bounds__(NTHR, 1)
timelstm_scan_kernel(const float* __restrict__ Wall, const float* __restrict__ Wallb,
                     const float* __restrict__ Wd,   const float* __restrict__ Wdb,
                     const float* __restrict__ ts,   float* __restrict__ out) {
    extern __shared__ float sm[];
    float* sWg = sm;                         // 80 rows x 512 (gates then decay)
    float* stg = sm + WTOT;                  // 2 x (h[32][132] + c[32][132])
    float* part = stg;                       // reduction region (reuses staging)

    const int tid  = threadIdx.x;
    const int lane = tid & 31;
    const int warp = tid >> 5;
    const int ks   = warp >> 2;              // 0..3 k-slice (finishers: ks==0)
    const int jg   = warp & 3;               // 0..3 j-group

    const int jt = blockIdx.x >> 2;
    const int bt = blockIdx.x & 3;
    const int j0 = jt * BJ;
    const int b0 = bt * BB;
    const int b  = b0 + lane;
    const int jbase = j0 + jg * 4;

    // ---- preload weights (once): rows 0..63 gates (g*16+jl), 64..79 decay ----
    for (int idx = tid; idx < 80 * 128; idx += NTHR) {
        int row = idx >> 7;
        int c4  = (idx & 127) << 2;
        const float* srcp = (row < 64)
            ? &Wall[(size_t)((row >> 4) * HDIM + j0 + (row & 15)) * HDIM + c4]
            : &Wd[(size_t)(j0 + row - 64) * HDIM + c4];
        *(float4*)&sWg[row * HDIM + c4] = *(const float4*)srcp;
    }
    // biases for finisher outputs (4 j each)
    float bF[4], bI[4], bO[4], bCt[4], bD[4];
#pragma unroll
    for (int ji = 0; ji < 4; ++ji) {
        int jj = jbase + ji;
        bF[ji]  = Wallb[0 * HDIM + jj];
        bI[ji]  = Wallb[1 * HDIM + jj];
        bO[ji]  = Wallb[2 * HDIM + jj];
        bCt[ji] = Wallb[3 * HDIM + jj];
        bD[ji]  = Wdb[jj];
    }
    __syncthreads();

    // weight thread base: +ji*512, +g*8192 (g=4 -> decay rows), +kcol
    const float* wbase = sWg + (jg * 4) * HDIM;
    // state LDS base: own batch row, own k-slice
    const float* hb = stg + lane * SROW + ks * 32;

    // staging writer mapping: 2 float4 of h + 2 of c per thread per quarter
    const int sr0 = tid >> 5;                 // rows 0..15
    const int scl = (tid & 31) << 2;          // cols 0..124
    float* sd0 = stg + sr0 * SROW + scl;
    float* sd1 = stg + (sr0 + 16) * SROW + scl;

    for (int s = 0; s < SEQ; ++s) {
        const int cur = s & 1, nxt = cur ^ 1;
        const float* hg = &g_h[cur][b0][0];
        const float* cg = &g_c[cur][b0][0];

        unsigned long long acc[4][5];
#pragma unroll
        for (int ji = 0; ji < 4; ++ji)
#pragma unroll
            for (int g = 0; g < 5; ++g) acc[ji][g] = 0ull;

        // ---- prologue: stage quarter 0 into buf0 ----
        {
            float4 h0 = __ldcg((const float4*)(hg + (size_t)sr0 * HDIM + scl));
            float4 h1 = __ldcg((const float4*)(hg + (size_t)(sr0 + 16) * HDIM + scl));
            float4 c0 = __ldcg((const float4*)(cg + (size_t)sr0 * HDIM + scl));
            float4 c1 = __ldcg((const float4*)(cg + (size_t)(sr0 + 16) * HDIM + scl));
            *(float4*)sd0 = h0; *(float4*)sd1 = h1;
            *(float4*)(sd0 + COFF) = c0; *(float4*)(sd1 + COFF) = c1;
        }
        __syncthreads();

#pragma unroll 1
        for (int q = 0; q < 4; ++q) {
            const int buf = q & 1;
            float4 nh0, nh1, nc0, nc1;
            if (q < 3) {   // prefetch next quarter while computing
                int ko = (q + 1) * 128 + scl;
                nh0 = __ldcg((const float4*)(hg + (size_t)sr0 * HDIM + ko));
                nh1 = __ldcg((const float4*)(hg + (size_t)(sr0 + 16) * HDIM + ko));
                nc0 = __ldcg((const float4*)(cg + (size_t)sr0 * HDIM + ko));
                nc1 = __ldcg((const float4*)(cg + (size_t)(sr0 + 16) * HDIM + ko));
            }

            const float* hp = hb + buf * BUFS;
            const float* wq = wbase + q * 128 + ks * 32;
#pragma unroll
            for (int it = 0; it < 8; ++it) {
                const int kk = it * 4;
                ulonglong2 hv = *(const ulonglong2*)(hp + kk);
                ulonglong2 cv = *(const ulonglong2*)(hp + COFF + kk);
#pragma unroll
                for (int ji = 0; ji < 4; ++ji) {
                    const float* wj = wq + ji * HDIM + kk;
                    ulonglong2 vF = *(const ulonglong2*)(wj + 0 * 8192);
                    acc[ji][0] = fma2(hv.x, vF.x, acc[ji][0]);
                    acc[ji][0] = fma2(hv.y, vF.y, acc[ji][0]);
                    ulonglong2 vI = *(const ulonglong2*)(wj + 1 * 8192);
                    acc[ji][1] = fma2(hv.x, vI.x, acc[ji][1]);
                    acc[ji][1] = fma2(hv.y, vI.y, acc[ji][1]);
                    ulonglong2 vO = *(const ulonglong2*)(wj + 2 * 8192);
                    acc[ji][2] = fma2(hv.x, vO.x, acc[ji][2]);
                    acc[ji][2] = fma2(hv.y, vO.y, acc[ji][2]);
                    ulonglong2 vC = *(const ulonglong2*)(wj + 3 * 8192);
                    acc[ji][3] = fma2(hv.x, vC.x, acc[ji][3]);
                    acc[ji][3] = fma2(hv.y, vC.y, acc[ji][3]);
                    ulonglong2 vD = *(const ulonglong2*)(wj + 4 * 8192);
                    acc[ji][4] = fma2(cv.x, vD.x, acc[ji][4]);
                    acc[ji][4] = fma2(cv.y, vD.y, acc[ji][4]);
                }
            }

            if (q < 3) {   // store next quarter into the other buffer
                float* nd0 = sd0 + (buf ^ 1) * BUFS;
                float* nd1 = sd1 + (buf ^ 1) * BUFS;
                *(float4*)nd0 = nh0; *(float4*)nd1 = nh1;
                *(float4*)(nd0 + COFF) = nc0; *(float4*)(nd1 + COFF) = nc1;
            }
            __syncthreads();
        }

        // ---- collapse packed halves ----
        float r[4][5];
#pragma unroll
        for (int ji = 0; ji < 4; ++ji)
#pragma unroll
            for (int g = 0; g < 5; ++g) r[ji][g] = red2(acc[ji][g]);

        // ---- k-partial exchange: ks=1..3 publish; ks=0 loads epilogue data ----
        float4 uF, uI, uO, uCt, cold4;
        float tv = 0.0f;
        if (ks) {
            float* pp = part + lane * PSTR_B + (ks - 1);
#pragma unroll
            for (int ji = 0; ji < 4; ++ji)
#pragma unroll
                for (int g = 0; g < 5; ++g)
                    pp[(jg * 4 + ji) * PSTR_J + g * 3] = r[ji][g];
        } else {
            const float* ub = &g_u[s][b][0];
            uF   = __ldcg((const float4*)(ub + 0 * HDIM + jbase));
            uI   = __ldcg((const float4*)(ub + 1 * HDIM + jbase));
            uO   = __ldcg((const float4*)(ub + 2 * HDIM + jbase));
            uCt  = __ldcg((const float4*)(ub + 3 * HDIM + jbase));
            cold4 = __ldcg((const float4*)&g_c[cur][b][jbase]);
            tv   = ts[(size_t)b * SEQ + s];
        }
        __syncthreads();

        // ---- epilogue on ks==0 warps: 1b x 4j per thread ----
        if (ks == 0) {
            const float* pp = part + lane * PSTR_B;
            float cn[4], hn[4];
            const float uf_[4]  = {uF.x, uF.y, uF.z, uF.w};
            const float ui_[4]  = {uI.x, uI.y, uI.z, uI.w};
            const float uo_[4]  = {uO.x, uO.y, uO.z, uO.w};
            const float uc_[4]  = {uCt.x, uCt.y, uCt.z, uCt.w};
            const float co_[4]  = {cold4.x, cold4.y, cold4.z, cold4.w};
#pragma unroll
            for (int ji = 0; ji < 4; ++ji) {
                const float* pj = pp + (jg * 4 + ji) * PSTR_J;
                float F  = r[ji][0] + pj[0]  + pj[1]  + pj[2]  + bF[ji]  + uf_[ji];
                float I_ = r[ji][1] + pj[3]  + pj[4]  + pj[5]  + bI[ji]  + ui_[ji];
                float O_ = r[ji][2] + pj[6]  + pj[7]  + pj[8]  + bO[ji]  + uo_[ji];
                float Ct = r[ji][3] + pj[9]  + pj[10] + pj[11] + bCt[ji] + uc_[ji];
                float D  = r[ji][4] + pj[12] + pj[13] + pj[14] + bD[ji];
                float f   = sigm(F);
                float ii  = sigm(I_);
                float oo  = sigm(O_);
                float ct  = sigm(Ct);
                float cs1 = tanhfast(D);
                float cadj = co_[ji] + cs1 * (tv - 1.0f);   // c - cs1 + cs1*t
                float cnew = f * cadj + ii * ct;
                cn[ji] = cnew;
                hn[ji] = oo * tanhfast(cnew);
            }
            *(float4*)&g_c[nxt][b][jbase] = make_float4(cn[0], cn[1], cn[2], cn[3]);
            *(float4*)&g_h[nxt][b][jbase] = make_float4(hn[0], hn[1], hn[2], hn[3]);
            *(float4*)&out[((size_t)b * SEQ + s) * HDIM + jbase] =
                make_float4(hn[0], hn[1], hn[2], hn[3]);
        }

        // ---- grid barrier ----
        __syncthreads();
        if (tid == 0) {
            volatile unsigned* vgen = &g_bar[1];
            unsigned gen = *vgen;
            __threadfence();
            if (atomicAdd(&g_bar[0], 1u) == NBLK - 1u) {
                g_bar[0] = 0u;
                __threadfence();
                *vgen = gen + 1u;
            } else {
                while (*vgen == gen) { }
            }
            __threadfence();
        }
        __syncthreads();
    }
}

// =====================================================================
extern "C" void kernel_launch(void* const* d_in, const int* in_sizes, int n_in,
                              void* d_out, int out_size) {
    const float* X     = (const float*)d_in[0];
    const float* T     = (const float*)d_in[1];
    const float* Wall  = (const float*)d_in[2];
    const float* Wallb = (const float*)d_in[3];
    const float* Uw    = (const float*)d_in[4];
    const float* Ubb   = (const float*)d_in[5];
    const float* Wd    = (const float*)d_in[6];
    const float* Wdb   = (const float*)d_in[7];
    float* out = (float*)d_out;

    void *hp, *cp, *bp;
    cudaGetSymbolAddress(&hp, g_h);
    cudaGetSymbolAddress(&cp, g_c);
    cudaGetSymbolAddress(&bp, g_bar);
    cudaMemsetAsync(hp, 0, sizeof(float) * 2 * BATCH * HDIM, 0);
    cudaMemsetAsync(cp, 0, sizeof(float) * 2 * BATCH * HDIM, 0);
    cudaMemsetAsync(bp, 0, sizeof(unsigned) * 2, 0);

    dim3 ugrid(G4 / 64, (BATCH * SEQ) / 64);
    u_gemm_kernel<<<ugrid, 128>>>(X, Uw, Ubb);

    cudaFuncSetAttribute(timelstm_scan_kernel,
                         cudaFuncAttributeMaxDynamicSharedMemorySize, SMEM_SCAN);
    timelstm_scan_kernel<<<NBLK, NTHR, SMEM_SCAN>>>(Wall, Wallb, Wd, Wdb, T, out);
}